// round 9
// baseline (speedup 1.0000x reference)
#include <cuda_runtime.h>

#define NB     131072      // 32768 centers * 4 species
#define MAXE   1048576
#define NCENT  32768

namespace {

constexpr float PI_F   = 3.14159265358979323846f;
constexpr float NORM_F = 0.17677669529663687f;   // 1/sqrt(32)

__device__ int    g_cnt[NB];
__device__ int    g_cur[NB];
__device__ int    g_off[NB];
__device__ int    g_blk[128];
__device__ float4 g_edges[MAXE];

// ------------------------------------------------------------ histogram (2 edges/thread)
__global__ void k_hist(const int* __restrict__ cidx,
                       const int* __restrict__ sidx, int n) {
    int i = blockIdx.x * blockDim.x + threadIdx.x;
    int e = i * 2;
    if (e + 1 < n) {
        int2 c = *reinterpret_cast<const int2*>(&cidx[e]);
        int2 s = *reinterpret_cast<const int2*>(&sidx[e]);
        atomicAdd(&g_cnt[c.x * 4 + s.x], 1);
        atomicAdd(&g_cnt[c.y * 4 + s.y], 1);
    } else if (e < n) {
        atomicAdd(&g_cnt[cidx[e] * 4 + sidx[e]], 1);
    }
}

// ------------------------------------------------------------ scan step A
__global__ void k_scanA() {            // 128 blocks x 256 threads
    __shared__ int sm[256];
    int t = threadIdx.x, blk = blockIdx.x;
    int base = blk * 1024 + t * 4;
    int4 c = *reinterpret_cast<const int4*>(&g_cnt[base]);
    int s = c.x + c.y + c.z + c.w;
    sm[t] = s;
    __syncthreads();
    #pragma unroll
    for (int off = 1; off < 256; off <<= 1) {
        int v = (t >= off) ? sm[t - off] : 0;
        __syncthreads();
        sm[t] += v;
        __syncthreads();
    }
    int ex = sm[t] - s;                // exclusive within CTA
    int4 o;
    o.x = ex; o.y = ex + c.x; o.z = o.y + c.y; o.w = o.z + c.z;
    *reinterpret_cast<int4*>(&g_cur[base]) = o;
    if (t == 255) g_blk[blk] = sm[255];
}

// ------------------------------------------------------------ scan step B+C fused
__global__ void k_scanC() {            // 128 blocks x 256 threads
    __shared__ int s_wsum[8];
    __shared__ int s_off;
    int t = threadIdx.x, blk = blockIdx.x;

    int contrib = (t < 128 && t < blk) ? g_blk[t] : 0;
    #pragma unroll
    for (int o = 16; o; o >>= 1)
        contrib += __shfl_down_sync(0xffffffffu, contrib, o);
    if ((t & 31) == 0) s_wsum[t >> 5] = contrib;
    __syncthreads();
    if (t == 0) {
        int a = 0;
        #pragma unroll
        for (int i = 0; i < 8; i++) a += s_wsum[i];
        s_off = a;
    }
    __syncthreads();
    int off = s_off;

    int i = blk * 256 + t;
    int4 v = *reinterpret_cast<int4*>(&g_cur[i * 4]);
    v.x += off; v.y += off; v.z += off; v.w += off;
    *reinterpret_cast<int4*>(&g_cur[i * 4]) = v;   // running cursor for scatter
    *reinterpret_cast<int4*>(&g_off[i * 4]) = v;   // immutable starts for accum
}

// ------------------------------------------------------------ scatter (2 edges/thread)
__global__ void k_scatter(const float* __restrict__ vec,
                          const int* __restrict__ cidx,
                          const int* __restrict__ sidx, int n) {
    int i = blockIdx.x * blockDim.x + threadIdx.x;
    int e = i * 2;
    if (e + 1 < n) {
        int2 c = *reinterpret_cast<const int2*>(&cidx[e]);
        int2 s = *reinterpret_cast<const int2*>(&sidx[e]);
        float2 v0 = *reinterpret_cast<const float2*>(&vec[3 * e]);
        float2 v1 = *reinterpret_cast<const float2*>(&vec[3 * e + 2]);
        float2 v2 = *reinterpret_cast<const float2*>(&vec[3 * e + 4]);
        int b0 = c.x * 4 + s.x;
        int b1 = c.y * 4 + s.y;
        int p0 = atomicAdd(&g_cur[b0], 1);
        int p1 = atomicAdd(&g_cur[b1], 1);
        g_edges[p0] = make_float4(v0.x, v0.y, v1.x, __int_as_float(b0));
        g_edges[p1] = make_float4(v1.y, v2.x, v2.y, __int_as_float(b1));
    } else if (e < n) {
        int b = cidx[e] * 4 + sidx[e];
        int p = atomicAdd(&g_cur[b], 1);
        g_edges[p] = make_float4(vec[3 * e], vec[3 * e + 1], vec[3 * e + 2],
                                 __int_as_float(b));
    }
}

// ------------------------------------------------------------ accumulate
// ONE WARP PER CENTER. Edges of a center are contiguous in g_edges (sorted by
// bucket = center*4+sp). Lanes load 32 edges/chunk coalesced, stage sh/rad to
// smem, then lane (k=lane>>1, half=lane&1) accumulates 4 species accumulators
// over per-sp segments (ballot). Final: plain st.v4 — every output element is
// written exactly once; empty centers write zeros (no memset needed).
__global__ __launch_bounds__(256, 4)
void k_accum(const float* __restrict__ W, float* __restrict__ out) {
    __shared__ float sW[384];
    __shared__ float s_sh[8][16 * 33];     // [warp][k*33 + edge]
    __shared__ float s_rad[8][8 * 132];    // [warp][q*132 + edge*4 + c]
    __shared__ int   s_sp[8][32];

    int t = threadIdx.x, w = t >> 5, lane = t & 31;
    for (int i = t; i < 384; i += 256) sW[i] = W[i];
    __syncthreads();

    int c  = blockIdx.x * 8 + w;           // center owned by this warp
    int s0 = g_off[c * 4];                 // start of center's edge range
    int e3 = g_cur[c * 4 + 3];             // end (post-scatter cursor = end)

    int myk  = lane >> 1;
    int half = lane & 1;
    int l    = (myk >= 9) ? 3 : ((myk >= 4) ? 2 : ((myk >= 1) ? 1 : 0));
    int q    = l * 2 + half;
    const float* shrow  = &s_sh[w][myk * 33];
    const float* radrow = &s_rad[w][q * 132];

    float acc[4][4];
    #pragma unroll
    for (int i = 0; i < 4; i++)
        #pragma unroll
        for (int j = 0; j < 4; j++) acc[i][j] = 0.f;

    for (int base = s0; base < e3; base += 32) {
        int idx = base + lane;
        int sp = -1;
        float4 v = make_float4(0.f, 0.f, 0.f, 0.f);
        if (idx < e3) { v = g_edges[idx]; sp = __float_as_int(v.w) & 3; }
        s_sp[w][lane] = sp;

        {
            float vx = v.x, vy = v.y, vz = v.z;
            float r2   = fmaf(vx, vx, fmaf(vy, vy, vz * vz)) + 1e-12f;
            float rinv = rsqrtf(r2);
            float r    = r2 * rinv;
            float x = vx * rinv, y = vy * rinv, z = vz * rinv;

            float a = (PI_F / 5.0f) * r;
            float sn, cs;
            __sincosf(a, &sn, &cs);
            float tt    = NORM_F * rinv;
            float two_c = 2.0f * cs;
            float phi[12];
            {
                float sm1 = 0.f, sc = sn;
                phi[0] = sc * tt;
                #pragma unroll
                for (int nn = 1; nn < 12; nn++) {
                    float s1 = fmaf(two_c, sc, -sm1);
                    sm1 = sc; sc = s1;
                    phi[nn] = sc * tt;
                }
            }

            // rad per l: 8 live accumulators streamed to smem
            const float4* w4 = reinterpret_cast<const float4*>(sW);
            #pragma unroll
            for (int ll = 0; ll < 4; ll++) {
                float r8[8];
                #pragma unroll
                for (int i = 0; i < 8; i++) r8[i] = 0.f;
                #pragma unroll
                for (int bb = 0; bb < 12; bb++) {
                    float p = phi[bb];
                    float4 w0 = w4[ll * 24 + bb * 2 + 0];
                    float4 w1 = w4[ll * 24 + bb * 2 + 1];
                    r8[0] = fmaf(p, w0.x, r8[0]);
                    r8[1] = fmaf(p, w0.y, r8[1]);
                    r8[2] = fmaf(p, w0.z, r8[2]);
                    r8[3] = fmaf(p, w0.w, r8[3]);
                    r8[4] = fmaf(p, w1.x, r8[4]);
                    r8[5] = fmaf(p, w1.y, r8[5]);
                    r8[6] = fmaf(p, w1.z, r8[6]);
                    r8[7] = fmaf(p, w1.w, r8[7]);
                }
                *reinterpret_cast<float4*>(&s_rad[w][(ll * 2 + 0) * 132 + lane * 4]) =
                    make_float4(r8[0], r8[1], r8[2], r8[3]);
                *reinterpret_cast<float4*>(&s_rad[w][(ll * 2 + 1) * 132 + lane * 4]) =
                    make_float4(r8[4], r8[5], r8[6], r8[7]);
            }

            float x2 = x * x, y2 = y * y, z2 = z * z;
            float* sr = &s_sh[w][lane];
            sr[0  * 33] = 0.28209479177387814f;
            sr[1  * 33] = 0.4886025119029199f * y;
            sr[2  * 33] = 0.4886025119029199f * z;
            sr[3  * 33] = 0.4886025119029199f * x;
            sr[4  * 33] = 1.0925484305920792f * x * y;
            sr[5  * 33] = 1.0925484305920792f * y * z;
            sr[6  * 33] = 0.31539156525252005f * fmaf(3.0f, z2, -1.0f);
            sr[7  * 33] = 1.0925484305920792f * x * z;
            sr[8  * 33] = 0.5462742152960396f * (x2 - y2);
            sr[9  * 33] = 0.5900435899266435f * y * fmaf(3.0f, x2, -y2);
            sr[10 * 33] = 2.890611442640554f  * x * y * z;
            sr[11 * 33] = 0.4570457994644658f * y * fmaf(5.0f, z2, -1.0f);
            sr[12 * 33] = 0.3731763325901154f * z * fmaf(5.0f, z2, -3.0f);
            sr[13 * 33] = 0.4570457994644658f * x * fmaf(5.0f, z2, -1.0f);
            sr[14 * 33] = 1.445305721320277f  * z * (x2 - y2);
            sr[15 * 33] = 0.5900435899266435f * x * (x2 - y2);
        }
        __syncwarp();

        // per-species contiguous segments within this chunk
        #pragma unroll
        for (int sp2 = 0; sp2 < 4; sp2++) {
            unsigned msk = __ballot_sync(0xffffffffu, sp == sp2);
            if (msk) {
                int lo  = __ffs(msk) - 1;
                int cnt = __popc(msk);
                float ax = 0.f, ay = 0.f, az = 0.f, aw = 0.f;
                for (int i = lo; i < lo + cnt; i++) {
                    float sk = shrow[i];
                    float4 r = *reinterpret_cast<const float4*>(&radrow[i * 4]);
                    ax = fmaf(sk, r.x, ax);
                    ay = fmaf(sk, r.y, ay);
                    az = fmaf(sk, r.z, az);
                    aw = fmaf(sk, r.w, aw);
                }
                acc[sp2][0] += ax;
                acc[sp2][1] += ay;
                acc[sp2][2] += az;
                acc[sp2][3] += aw;
            }
        }
        __syncwarp();
    }

    // write: every output element exactly once (also covers empty centers)
    float* p = out + (size_t)c * 512 + myk * 32 + half * 4;
    #pragma unroll
    for (int sp2 = 0; sp2 < 4; sp2++)
        *reinterpret_cast<float4*>(p + sp2 * 8) =
            make_float4(acc[sp2][0], acc[sp2][1], acc[sp2][2], acc[sp2][3]);
}

} // namespace

extern "C" void kernel_launch(void* const* d_in, const int* in_sizes, int n_in,
                              void* d_out, int out_size)
{
    const float* vectors = (const float*)d_in[0];
    const float* W       = (const float*)d_in[1];
    const int*   cidx    = (const int*)d_in[2];
    const int*   sidx    = (const int*)d_in[3];
    float*       out     = (float*)d_out;

    int n_edges = in_sizes[2];

    static void* cnt_ptr = nullptr;
    if (!cnt_ptr) cudaGetSymbolAddress(&cnt_ptr, g_cnt);

    cudaMemsetAsync(cnt_ptr, 0, NB * sizeof(int), 0);

    k_hist<<<(n_edges / 2 + 255) / 256, 256>>>(cidx, sidx, n_edges);
    k_scanA<<<128, 256>>>();
    k_scanC<<<128, 256>>>();
    k_scatter<<<(n_edges / 2 + 255) / 256, 256>>>(vectors, cidx, sidx, n_edges);
    k_accum<<<NCENT / 8, 256>>>(W, out);   // one warp per center; writes all outputs
}

// round 10
// speedup vs baseline: 1.0396x; 1.0396x over previous
#include <cuda_runtime.h>

#define NB     131072      // 32768 centers * 4 species
#define MAXE   1048576

namespace {

constexpr float PI_F   = 3.14159265358979323846f;
constexpr float NORM_F = 0.17677669529663687f;   // 1/sqrt(32)

typedef unsigned long long ull;

__device__ int    g_cnt[NB];
__device__ int    g_cur[NB];
__device__ int    g_blk[128];
__device__ float4 g_edges[MAXE];

__device__ __forceinline__ void red_add_v4(float* p, float a, float b, float c, float d) {
    unsigned long long gp = __cvta_generic_to_global(p);
    asm volatile("red.global.add.v4.f32 [%0], {%1, %2, %3, %4};"
                 :: "l"(gp), "f"(a), "f"(b), "f"(c), "f"(d)
                 : "memory");
}

// ---- packed fp32x2 helpers (sm_103a FFMA2 path) ----
__device__ __forceinline__ ull pack2(float lo, float hi) {
    ull r; asm("mov.b64 %0, {%1, %2};" : "=l"(r) : "f"(lo), "f"(hi)); return r;
}
__device__ __forceinline__ void unpack2(ull v, float& lo, float& hi) {
    asm("mov.b64 {%0, %1}, %2;" : "=f"(lo), "=f"(hi) : "l"(v));
}
__device__ __forceinline__ ull ffma2(ull a, ull b, ull c) {
    ull d; asm("fma.rn.f32x2 %0, %1, %2, %3;" : "=l"(d) : "l"(a), "l"(b), "l"(c));
    return d;
}

// ------------------------------------------------------------ histogram (2 edges/thread)
__global__ void k_hist(const int* __restrict__ cidx,
                       const int* __restrict__ sidx, int n) {
    int i = blockIdx.x * blockDim.x + threadIdx.x;
    int e = i * 2;
    if (e + 1 < n) {
        int2 c = *reinterpret_cast<const int2*>(&cidx[e]);
        int2 s = *reinterpret_cast<const int2*>(&sidx[e]);
        atomicAdd(&g_cnt[c.x * 4 + s.x], 1);
        atomicAdd(&g_cnt[c.y * 4 + s.y], 1);
    } else if (e < n) {
        atomicAdd(&g_cnt[cidx[e] * 4 + sidx[e]], 1);
    }
}

// ------------------------------------------------------------ scan step A
__global__ void k_scanA() {            // 128 blocks x 256 threads
    __shared__ int sm[256];
    int t = threadIdx.x, blk = blockIdx.x;
    int base = blk * 1024 + t * 4;
    int4 c = *reinterpret_cast<const int4*>(&g_cnt[base]);
    int s = c.x + c.y + c.z + c.w;
    sm[t] = s;
    __syncthreads();
    #pragma unroll
    for (int off = 1; off < 256; off <<= 1) {
        int v = (t >= off) ? sm[t - off] : 0;
        __syncthreads();
        sm[t] += v;
        __syncthreads();
    }
    int ex = sm[t] - s;                // exclusive within CTA
    int4 o;
    o.x = ex; o.y = ex + c.x; o.z = o.y + c.y; o.w = o.z + c.z;
    *reinterpret_cast<int4*>(&g_cur[base]) = o;
    if (t == 255) g_blk[blk] = sm[255];
}

// ------------------------------------------------------------ scan step B+C fused
__global__ void k_scanC() {            // 128 blocks x 256 threads
    __shared__ int s_wsum[8];
    __shared__ int s_off;
    int t = threadIdx.x, blk = blockIdx.x;

    int contrib = (t < 128 && t < blk) ? g_blk[t] : 0;
    #pragma unroll
    for (int o = 16; o; o >>= 1)
        contrib += __shfl_down_sync(0xffffffffu, contrib, o);
    if ((t & 31) == 0) s_wsum[t >> 5] = contrib;
    __syncthreads();
    if (t == 0) {
        int a = 0;
        #pragma unroll
        for (int i = 0; i < 8; i++) a += s_wsum[i];
        s_off = a;
    }
    __syncthreads();
    int off = s_off;

    int i = blk * 256 + t;
    int4 v = *reinterpret_cast<int4*>(&g_cur[i * 4]);
    v.x += off; v.y += off; v.z += off; v.w += off;
    *reinterpret_cast<int4*>(&g_cur[i * 4]) = v;
}

// ------------------------------------------------------------ scatter (1 edge/thread)
__global__ void k_scatter(const float* __restrict__ vec,
                          const int* __restrict__ cidx,
                          const int* __restrict__ sidx, int n) {
    int e = blockIdx.x * blockDim.x + threadIdx.x;
    if (e >= n) return;
    int b = cidx[e] * 4 + sidx[e];
    int p = atomicAdd(&g_cur[b], 1);
    g_edges[p] = make_float4(vec[3 * e], vec[3 * e + 1], vec[3 * e + 2],
                             __int_as_float(b));
}

// ------------------------------------------------------------ accumulate
// 256 threads = 8 warps; each warp owns 32 consecutive sorted edges.
// Packed f32x2 FMA in the rad projection and segment-reduce loops.
__global__ __launch_bounds__(256, 4)
void k_accum(const float* __restrict__ W, float* __restrict__ out, int n) {
    __shared__ __align__(16) float sW[384];
    __shared__ __align__(16) float s_sh[8][16 * 33];   // [warp][k*33 + edge]
    __shared__ __align__(16) float s_rad[8][8 * 132];  // [warp][q*132 + edge*4 + c]

    int t = threadIdx.x, w = t >> 5, lane = t & 31;
    for (int i = t; i < 384; i += 256) sW[i] = W[i];
    __syncthreads();

    int e = blockIdx.x * 256 + w * 32 + lane;
    int b = -1;
    float4 v = make_float4(0.f, 0.f, 0.f, 0.f);
    if (e < n) { v = g_edges[e]; b = __float_as_int(v.w); }

    {
        float vx = v.x, vy = v.y, vz = v.z;
        float r2   = fmaf(vx, vx, fmaf(vy, vy, vz * vz)) + 1e-12f;
        float rinv = rsqrtf(r2);
        float r    = r2 * rinv;
        float x = vx * rinv, y = vy * rinv, z = vz * rinv;
        if (b < 0) { x = 0.f; y = 0.f; z = 0.f; }

        // phi[b] = sin(pi/5 * r * (b+1)) / r * NORM  via Chebyshev recurrence
        float a = (PI_F / 5.0f) * r;
        float s0, c0;
        __sincosf(a, &s0, &c0);
        float tt    = (b >= 0) ? (NORM_F * rinv) : 0.f;
        float two_c = 2.0f * c0;
        float phi[12];
        {
            float sm1 = 0.f, sc = s0;
            phi[0] = sc * tt;
            #pragma unroll
            for (int nn = 1; nn < 12; nn++) {
                float s1 = fmaf(two_c, sc, -sm1);
                sm1 = sc; sc = s1;
                phi[nn] = sc * tt;
            }
        }

        // rad per l with packed f32x2 FMA: 4 packed accumulators per l
        const ulonglong2* wp = reinterpret_cast<const ulonglong2*>(sW);
        #pragma unroll
        for (int l = 0; l < 4; l++) {
            ull r01 = 0ull, r23 = 0ull, r45 = 0ull, r67 = 0ull;  // {0.f,0.f}
            #pragma unroll
            for (int bb = 0; bb < 12; bb++) {
                ull pp = pack2(phi[bb], phi[bb]);
                ulonglong2 wa = wp[l * 12 + bb];   // 16B = {w0w1, w2w3} ... row of 8 floats = 2 ulonglong2
                ulonglong2 wbq = wp[l * 12 + bb];
                (void)wbq;
                // sW row for (l,bb) is 8 floats = 32 bytes = 2 ulonglong2 entries
                ulonglong2 w_lo = reinterpret_cast<const ulonglong2*>(sW)[(l * 96 + bb * 8) / 4];
                ulonglong2 w_hi = reinterpret_cast<const ulonglong2*>(sW)[(l * 96 + bb * 8) / 4 + 1];
                (void)wa;
                r01 = ffma2(pp, w_lo.x, r01);
                r23 = ffma2(pp, w_lo.y, r23);
                r45 = ffma2(pp, w_hi.x, r45);
                r67 = ffma2(pp, w_hi.y, r67);
            }
            *reinterpret_cast<ulonglong2*>(&s_rad[w][(l * 2 + 0) * 132 + lane * 4]) =
                make_ulonglong2(r01, r23);
            *reinterpret_cast<ulonglong2*>(&s_rad[w][(l * 2 + 1) * 132 + lane * 4]) =
                make_ulonglong2(r45, r67);
        }

        // sh straight to smem
        float x2 = x * x, y2 = y * y, z2 = z * z;
        float* sr = &s_sh[w][lane];
        sr[0  * 33] = 0.28209479177387814f;
        sr[1  * 33] = 0.4886025119029199f * y;
        sr[2  * 33] = 0.4886025119029199f * z;
        sr[3  * 33] = 0.4886025119029199f * x;
        sr[4  * 33] = 1.0925484305920792f * x * y;
        sr[5  * 33] = 1.0925484305920792f * y * z;
        sr[6  * 33] = 0.31539156525252005f * fmaf(3.0f, z2, -1.0f);
        sr[7  * 33] = 1.0925484305920792f * x * z;
        sr[8  * 33] = 0.5462742152960396f * (x2 - y2);
        sr[9  * 33] = 0.5900435899266435f * y * fmaf(3.0f, x2, -y2);
        sr[10 * 33] = 2.890611442640554f  * x * y * z;
        sr[11 * 33] = 0.4570457994644658f * y * fmaf(5.0f, z2, -1.0f);
        sr[12 * 33] = 0.3731763325901154f * z * fmaf(5.0f, z2, -3.0f);
        sr[13 * 33] = 0.4570457994644658f * x * fmaf(5.0f, z2, -1.0f);
        sr[14 * 33] = 1.445305721320277f  * z * (x2 - y2);
        sr[15 * 33] = 0.5900435899266435f * x * (x2 - y2);
    }
    __syncwarp();

    // segment detection over sorted bucket ids
    int b_up = __shfl_up_sync(0xffffffffu, b, 1);
    bool head = (lane == 0) || (b != b_up);
    unsigned hm = __ballot_sync(0xffffffffu, head);

    int myk  = lane >> 1;
    int half = lane & 1;
    int l    = (myk >= 9) ? 3 : ((myk >= 4) ? 2 : ((myk >= 1) ? 1 : 0));
    int q    = l * 2 + half;
    const float* shrow  = &s_sh[w][myk * 33];
    const float* radrow = &s_rad[w][q * 132];

    unsigned m = hm;
    while (m) {
        int s = __ffs(m) - 1;
        m &= m - 1;
        int e2 = m ? (__ffs(m) - 1) : 32;
        int bs = __shfl_sync(0xffffffffu, b, s);
        if (bs >= 0) {
            ull a01 = 0ull, a23 = 0ull;
            for (int i = s; i < e2; i++) {
                float sk = shrow[i];
                ull shp = pack2(sk, sk);
                ulonglong2 rr = *reinterpret_cast<const ulonglong2*>(&radrow[i * 4]);
                a01 = ffma2(shp, rr.x, a01);
                a23 = ffma2(shp, rr.y, a23);
            }
            float ax, ay, az, aw;
            unpack2(a01, ax, ay);
            unpack2(a23, az, aw);
            float* p = out + ((bs >> 2) * 512 + myk * 32 + (bs & 3) * 8 + half * 4);
            red_add_v4(p, ax, ay, az, aw);
        }
    }
}

} // namespace

extern "C" void kernel_launch(void* const* d_in, const int* in_sizes, int n_in,
                              void* d_out, int out_size)
{
    const float* vectors = (const float*)d_in[0];
    const float* W       = (const float*)d_in[1];
    const int*   cidx    = (const int*)d_in[2];
    const int*   sidx    = (const int*)d_in[3];
    float*       out     = (float*)d_out;

    int n_edges = in_sizes[2];

    static void* cnt_ptr = nullptr;
    if (!cnt_ptr) cudaGetSymbolAddress(&cnt_ptr, g_cnt);

    cudaMemsetAsync(d_out, 0, (size_t)out_size * sizeof(float), 0);
    cudaMemsetAsync(cnt_ptr, 0, NB * sizeof(int), 0);

    k_hist<<<(n_edges / 2 + 255) / 256, 256>>>(cidx, sidx, n_edges);
    k_scanA<<<128, 256>>>();
    k_scanC<<<128, 256>>>();
    k_scatter<<<(n_edges + 255) / 256, 256>>>(vectors, cidx, sidx, n_edges);
    k_accum<<<(n_edges + 255) / 256, 256>>>(W, out, n_edges);
}

// round 11
// speedup vs baseline: 1.0446x; 1.0048x over previous
#include <cuda_runtime.h>

#define NB     131072      // 32768 centers * 4 species
#define MAXE   1048576

namespace {

constexpr float PI_F   = 3.14159265358979323846f;
constexpr float NORM_F = 0.17677669529663687f;   // 1/sqrt(32)

typedef unsigned long long ull;

__device__ int    g_cnt[NB];
__device__ int    g_cur[NB];
__device__ int    g_off[NB];
__device__ int    g_blk[128];
__device__ float4 g_edges[MAXE];

// ---- packed fp32x2 helpers (sm_103a FFMA2 path) ----
__device__ __forceinline__ ull pack2(float lo, float hi) {
    ull r; asm("mov.b64 %0, {%1, %2};" : "=l"(r) : "f"(lo), "f"(hi)); return r;
}
__device__ __forceinline__ void unpack2(ull v, float& lo, float& hi) {
    asm("mov.b64 {%0, %1}, %2;" : "=f"(lo), "=f"(hi) : "l"(v));
}
__device__ __forceinline__ ull ffma2(ull a, ull b, ull c) {
    ull d; asm("fma.rn.f32x2 %0, %1, %2, %3;" : "=l"(d) : "l"(a), "l"(b), "l"(c));
    return d;
}

// ------------------------------------------------------------ histogram (2 edges/thread)
__global__ void k_hist(const int* __restrict__ cidx,
                       const int* __restrict__ sidx, int n) {
    int i = blockIdx.x * blockDim.x + threadIdx.x;
    int e = i * 2;
    if (e + 1 < n) {
        int2 c = *reinterpret_cast<const int2*>(&cidx[e]);
        int2 s = *reinterpret_cast<const int2*>(&sidx[e]);
        atomicAdd(&g_cnt[c.x * 4 + s.x], 1);
        atomicAdd(&g_cnt[c.y * 4 + s.y], 1);
    } else if (e < n) {
        atomicAdd(&g_cnt[cidx[e] * 4 + sidx[e]], 1);
    }
}

// ------------------------------------------------------------ scan step A
__global__ void k_scanA() {            // 128 blocks x 256 threads
    __shared__ int sm[256];
    int t = threadIdx.x, blk = blockIdx.x;
    int base = blk * 1024 + t * 4;
    int4 c = *reinterpret_cast<const int4*>(&g_cnt[base]);
    int s = c.x + c.y + c.z + c.w;
    sm[t] = s;
    __syncthreads();
    #pragma unroll
    for (int off = 1; off < 256; off <<= 1) {
        int v = (t >= off) ? sm[t - off] : 0;
        __syncthreads();
        sm[t] += v;
        __syncthreads();
    }
    int ex = sm[t] - s;                // exclusive within CTA
    int4 o;
    o.x = ex; o.y = ex + c.x; o.z = o.y + c.y; o.w = o.z + c.z;
    *reinterpret_cast<int4*>(&g_cur[base]) = o;
    if (t == 255) g_blk[blk] = sm[255];
}

// ------------------------------------------------------------ scan step B+C fused
__global__ void k_scanC() {            // 128 blocks x 256 threads
    __shared__ int s_wsum[8];
    __shared__ int s_off;
    int t = threadIdx.x, blk = blockIdx.x;

    int contrib = (t < 128 && t < blk) ? g_blk[t] : 0;
    #pragma unroll
    for (int o = 16; o; o >>= 1)
        contrib += __shfl_down_sync(0xffffffffu, contrib, o);
    if ((t & 31) == 0) s_wsum[t >> 5] = contrib;
    __syncthreads();
    if (t == 0) {
        int a = 0;
        #pragma unroll
        for (int i = 0; i < 8; i++) a += s_wsum[i];
        s_off = a;
    }
    __syncthreads();
    int off = s_off;

    int i = blk * 256 + t;
    int4 v = *reinterpret_cast<int4*>(&g_cur[i * 4]);
    v.x += off; v.y += off; v.z += off; v.w += off;
    *reinterpret_cast<int4*>(&g_cur[i * 4]) = v;   // running cursor (scatter)
    *reinterpret_cast<int4*>(&g_off[i * 4]) = v;   // immutable starts (accum)
}

// ------------------------------------------------------------ scatter (1 edge/thread)
__global__ void k_scatter(const float* __restrict__ vec,
                          const int* __restrict__ cidx,
                          const int* __restrict__ sidx, int n) {
    int e = blockIdx.x * blockDim.x + threadIdx.x;
    if (e >= n) return;
    int b = cidx[e] * 4 + sidx[e];
    int p = atomicAdd(&g_cur[b], 1);
    g_edges[p] = make_float4(vec[3 * e], vec[3 * e + 1], vec[3 * e + 2],
                             __int_as_float(b));
}

// ------------------------------------------------------------ accumulate
// ONE WARP OWNS 8 CONSECUTIVE BUCKETS (their edges are contiguous). Edges are
// processed in coalesced 32-chunks; a running per-lane accumulator is carried
// across chunks and PLAIN-STORED on bucket change. No output atomics, no
// output memset (empty buckets get explicit zero stores).
__global__ __launch_bounds__(256, 4)
void k_accum(const float* __restrict__ W, float* __restrict__ out, int n) {
    __shared__ __align__(16) float sW[384];
    __shared__ __align__(16) float s_sh[8][16 * 33];   // [warp][k*33 + edge]
    __shared__ __align__(16) float s_rad[8][8 * 132];  // [warp][q*132 + edge*4 + c]

    int t = threadIdx.x, w = t >> 5, lane = t & 31;
    for (int i = t; i < 384; i += 256) sW[i] = W[i];
    __syncthreads();

    int ww = blockIdx.x * 8 + w;           // warp id, 16384 total
    int b0 = ww * 8;                       // first of 8 owned buckets
    int s0 = g_off[b0];
    int e3 = (b0 + 8 < NB) ? g_off[b0 + 8] : n;

    int myk  = lane >> 1;
    int half = lane & 1;
    int l    = (myk >= 9) ? 3 : ((myk >= 4) ? 2 : ((myk >= 1) ? 1 : 0));
    int q    = l * 2 + half;
    const float* shrow  = &s_sh[w][myk * 33];
    const float* radrow = &s_rad[w][q * 132];

    int curb = -1;
    ull a01 = 0ull, a23 = 0ull;

    for (int base = s0; base < e3; base += 32) {
        int idx = base + lane;
        int b = -1;
        float4 v = make_float4(0.f, 0.f, 0.f, 0.f);
        if (idx < e3) { v = g_edges[idx]; b = __float_as_int(v.w); }

        {
            float vx = v.x, vy = v.y, vz = v.z;
            float r2   = fmaf(vx, vx, fmaf(vy, vy, vz * vz)) + 1e-12f;
            float rinv = rsqrtf(r2);
            float r    = r2 * rinv;
            float x = vx * rinv, y = vy * rinv, z = vz * rinv;

            float a = (PI_F / 5.0f) * r;
            float sn, cs;
            __sincosf(a, &sn, &cs);
            float tt    = NORM_F * rinv;
            float two_c = 2.0f * cs;
            float phi[12];
            {
                float sm1 = 0.f, sc = sn;
                phi[0] = sc * tt;
                #pragma unroll
                for (int nn = 1; nn < 12; nn++) {
                    float s1 = fmaf(two_c, sc, -sm1);
                    sm1 = sc; sc = s1;
                    phi[nn] = sc * tt;
                }
            }

            // rad per l with packed f32x2 FMA (W rows are uniform smem loads)
            #pragma unroll
            for (int ll = 0; ll < 4; ll++) {
                ull r01 = 0ull, r23 = 0ull, r45 = 0ull, r67 = 0ull;
                #pragma unroll
                for (int bb = 0; bb < 12; bb++) {
                    ull pp = pack2(phi[bb], phi[bb]);
                    ulonglong2 w_lo = reinterpret_cast<const ulonglong2*>(sW)[(ll * 96 + bb * 8) / 4];
                    ulonglong2 w_hi = reinterpret_cast<const ulonglong2*>(sW)[(ll * 96 + bb * 8) / 4 + 1];
                    r01 = ffma2(pp, w_lo.x, r01);
                    r23 = ffma2(pp, w_lo.y, r23);
                    r45 = ffma2(pp, w_hi.x, r45);
                    r67 = ffma2(pp, w_hi.y, r67);
                }
                *reinterpret_cast<ulonglong2*>(&s_rad[w][(ll * 2 + 0) * 132 + lane * 4]) =
                    make_ulonglong2(r01, r23);
                *reinterpret_cast<ulonglong2*>(&s_rad[w][(ll * 2 + 1) * 132 + lane * 4]) =
                    make_ulonglong2(r45, r67);
            }

            float x2 = x * x, y2 = y * y, z2 = z * z;
            float* sr = &s_sh[w][lane];
            sr[0  * 33] = 0.28209479177387814f;
            sr[1  * 33] = 0.4886025119029199f * y;
            sr[2  * 33] = 0.4886025119029199f * z;
            sr[3  * 33] = 0.4886025119029199f * x;
            sr[4  * 33] = 1.0925484305920792f * x * y;
            sr[5  * 33] = 1.0925484305920792f * y * z;
            sr[6  * 33] = 0.31539156525252005f * fmaf(3.0f, z2, -1.0f);
            sr[7  * 33] = 1.0925484305920792f * x * z;
            sr[8  * 33] = 0.5462742152960396f * (x2 - y2);
            sr[9  * 33] = 0.5900435899266435f * y * fmaf(3.0f, x2, -y2);
            sr[10 * 33] = 2.890611442640554f  * x * y * z;
            sr[11 * 33] = 0.4570457994644658f * y * fmaf(5.0f, z2, -1.0f);
            sr[12 * 33] = 0.3731763325901154f * z * fmaf(5.0f, z2, -3.0f);
            sr[13 * 33] = 0.4570457994644658f * x * fmaf(5.0f, z2, -1.0f);
            sr[14 * 33] = 1.445305721320277f  * z * (x2 - y2);
            sr[15 * 33] = 0.5900435899266435f * x * (x2 - y2);
        }
        __syncwarp();

        // segment detection over sorted bucket ids (ascending within chunk)
        int b_up = __shfl_up_sync(0xffffffffu, b, 1);
        bool head = (lane == 0) || (b != b_up);
        unsigned hm = __ballot_sync(0xffffffffu, head);

        unsigned m = hm;
        while (m) {
            int s = __ffs(m) - 1;
            m &= m - 1;
            int e2 = m ? (__ffs(m) - 1) : 32;
            int bs = __shfl_sync(0xffffffffu, b, s);
            if (bs >= 0) {
                if (bs != curb) {
                    if (curb >= 0) {
                        float ax, ay, az, aw;
                        unpack2(a01, ax, ay);
                        unpack2(a23, az, aw);
                        float* p = out + ((curb >> 2) * 512 + myk * 32 + (curb & 3) * 8 + half * 4);
                        *reinterpret_cast<float4*>(p) = make_float4(ax, ay, az, aw);
                    }
                    curb = bs;
                    a01 = 0ull; a23 = 0ull;
                }
                for (int i = s; i < e2; i++) {
                    float sk = shrow[i];
                    ull shp = pack2(sk, sk);
                    ulonglong2 rr = *reinterpret_cast<const ulonglong2*>(&radrow[i * 4]);
                    a01 = ffma2(shp, rr.x, a01);
                    a23 = ffma2(shp, rr.y, a23);
                }
            }
        }
        __syncwarp();
    }

    // final flush
    if (curb >= 0) {
        float ax, ay, az, aw;
        unpack2(a01, ax, ay);
        unpack2(a23, az, aw);
        float* p = out + ((curb >> 2) * 512 + myk * 32 + (curb & 3) * 8 + half * 4);
        *reinterpret_cast<float4*>(p) = make_float4(ax, ay, az, aw);
    }

    // empty buckets: write zeros exactly once
    bool is_empty = false;
    if (lane < 8) {
        int bkt = b0 + lane;
        int st  = g_off[bkt];
        int en  = (bkt + 1 < NB) ? g_off[bkt + 1] : n;
        is_empty = (st == en);
    }
    unsigned em = __ballot_sync(0xffffffffu, is_empty);
    while (em) {
        int j = __ffs(em) - 1;
        em &= em - 1;
        int bkt = b0 + j;
        float* p = out + ((bkt >> 2) * 512 + myk * 32 + (bkt & 3) * 8 + half * 4);
        *reinterpret_cast<float4*>(p) = make_float4(0.f, 0.f, 0.f, 0.f);
    }
}

} // namespace

extern "C" void kernel_launch(void* const* d_in, const int* in_sizes, int n_in,
                              void* d_out, int out_size)
{
    const float* vectors = (const float*)d_in[0];
    const float* W       = (const float*)d_in[1];
    const int*   cidx    = (const int*)d_in[2];
    const int*   sidx    = (const int*)d_in[3];
    float*       out     = (float*)d_out;

    int n_edges = in_sizes[2];

    static void* cnt_ptr = nullptr;
    if (!cnt_ptr) cudaGetSymbolAddress(&cnt_ptr, g_cnt);

    // 6 launches/iter -> ncu -s 5 lands on k_accum (finally observable)
    cudaMemsetAsync(cnt_ptr, 0, NB * sizeof(int), 0);
    k_hist<<<(n_edges / 2 + 255) / 256, 256>>>(cidx, sidx, n_edges);
    k_scanA<<<128, 256>>>();
    k_scanC<<<128, 256>>>();
    k_scatter<<<(n_edges + 255) / 256, 256>>>(vectors, cidx, sidx, n_edges);
    k_accum<<<NB / 8 / 8, 256>>>(W, out, n_edges);   // 16384 warps, 8 buckets each
}